// round 1
// baseline (speedup 1.0000x reference)
#include <cuda_runtime.h>
#include <cstdint>

// Problem constants
#define BB   32
#define TT   64
#define SS   64
#define HH   256
#define VV   32000
#define NBLK 128   // persistent recurrence grid (must be <= SM count for residency)

// ---------------------------------------------------------------------------
// Device scratch (static allocation only; no cudaMalloc allowed)
// ---------------------------------------------------------------------------
__device__ __align__(16) float g_Wcat[256 * 1024];     // [k][ qproj(256) | Whz | Whr | Whh ]
__device__ __align__(16) float g_bcat[1024];
__device__ __align__(16) float g_Wann[256 * 1024];     // [k][ W1_ann(256) | Wiz_c | Wir_c | Wih_c ]
__device__ __align__(16) float g_Wx[256 * 768];        // [k][ Wiz_x | Wir_x | Wih_x ]
__device__ __align__(16) float g_annprojT[256 * 2048]; // [h][b*S+s]  (transposed for phase-A access)
__device__ __align__(16) float g_annWi[2048 * 768];    // [(b*S+s)][768]
__device__ __align__(16) float g_xproj[2048 * 768];    // [(t*B+b)][768]  includes biz/bir/bih
__device__ __align__(16) float g_hcat[32 * 1024];      // [b][1024]
__device__ __align__(16) float g_upart[32 * 2048];     // [slice][b*S+s]
__device__ __align__(16) float g_hbuf[32 * 256];
__device__ __align__(16) float g_hiddens[2048 * 256];  // [(b*T+t)][256]

__device__ unsigned g_bar_count;
__device__ volatile unsigned g_bar_gen;

// ---------------------------------------------------------------------------
// Grid-wide barrier (all NBLK CTAs resident in one wave)
// ---------------------------------------------------------------------------
__device__ __forceinline__ void grid_barrier() {
    __syncthreads();
    if (threadIdx.x == 0) {
        unsigned gen = g_bar_gen;
        __threadfence();
        if (atomicAdd(&g_bar_count, 1u) == NBLK - 1) {
            atomicExch(&g_bar_count, 0u);
            __threadfence();
            g_bar_gen = gen + 1;
        } else {
            while (g_bar_gen == gen) { /* spin on L2 */ }
            __threadfence();
        }
    }
    __syncthreads();
}

// ---------------------------------------------------------------------------
// K0: build fused weight matrices
// ---------------------------------------------------------------------------
__global__ void prep_kernel(const float* __restrict__ W1,
                            const float* __restrict__ Wiz, const float* __restrict__ Wir,
                            const float* __restrict__ Wih,
                            const float* __restrict__ Whz, const float* __restrict__ bhz,
                            const float* __restrict__ Whr, const float* __restrict__ bhr,
                            const float* __restrict__ Whh, const float* __restrict__ bhh) {
    int idx = blockIdx.x * blockDim.x + threadIdx.x;
    int stride = gridDim.x * blockDim.x;
    for (int i = idx; i < 256 * 1024; i += stride) {
        int k = i >> 10, j = i & 1023;
        float wc, wa;
        if (j < 256)      { wc = W1[k * 256 + j];          wa = W1[(256 + k) * 256 + j]; }
        else if (j < 512) { wc = Whz[k * 256 + j - 256];   wa = Wiz[k * 256 + j - 256]; }
        else if (j < 768) { wc = Whr[k * 256 + j - 512];   wa = Wir[k * 256 + j - 512]; }
        else              { wc = Whh[k * 256 + j - 768];   wa = Wih[k * 256 + j - 768]; }
        g_Wcat[i] = wc; g_Wann[i] = wa;
    }
    for (int i = idx; i < 256 * 768; i += stride) {
        int k = i / 768, j = i % 768;
        float w;
        if (j < 256)      w = Wiz[(256 + k) * 256 + j];
        else if (j < 512) w = Wir[(256 + k) * 256 + j - 256];
        else              w = Wih[(256 + k) * 256 + j - 512];
        g_Wx[i] = w;
    }
    for (int i = idx; i < 1024; i += stride) {
        float bv = 0.f;
        if (i >= 256 && i < 512)      bv = bhz[i - 256];
        else if (i >= 512 && i < 768) bv = bhr[i - 512];
        else if (i >= 768)            bv = bhh[i - 768];
        g_bcat[i] = bv;
    }
}

// ---------------------------------------------------------------------------
// Shared SGEMM: C = A(2048 x 256) * B(256 x N), BM=BN=128, BK=8, 8x8 micro-tile
// MODE 1: A=annotations, B=g_Wann  -> annprojT (+b1) / annWi
// MODE 2: A=gather(emb, inputs), B=g_Wx -> xproj (+biz/bir/bih)
// MODE 4: A=g_hiddens, B=Wout -> d_out (+bout)
// ---------------------------------------------------------------------------
template <int MODE>
__global__ void __launch_bounds__(256, 2)
sgemm_k(const float* __restrict__ Aarg, const float* __restrict__ Barg,
        const float* __restrict__ bias0, const float* __restrict__ bias1,
        const float* __restrict__ bias2, float* __restrict__ Cout,
        const int* __restrict__ tok_inputs, const float* __restrict__ emb, int N) {
    __shared__ __align__(16) float As[2][8][128];
    __shared__ __align__(16) float Bs[2][8][128];
    __shared__ int tok[128];

    const int tid = threadIdx.x;
    const int row0 = blockIdx.x * 128;
    const int col0 = blockIdx.y * 128;

    if (MODE == 2) {
        if (tid < 128) {
            int r = row0 + tid;
            int t = r >> 5, b = r & 31;
            tok[tid] = tok_inputs[b * TT + t];
        }
        __syncthreads();
    }

    const float* Bm = (MODE == 1) ? g_Wann : (MODE == 2) ? g_Wx : Barg;
    const float* Abase = (MODE == 4) ? g_hiddens : Aarg;

    const int am  = tid >> 1;
    const int ak  = (tid & 1) * 4;
    const int bk  = tid >> 5;
    const int bn4 = (tid & 31) * 4;

    const float* Arow = (MODE == 2) ? (emb + (size_t)tok[am] * 256)
                                    : (Abase + (size_t)(row0 + am) * 256);
    const float* Bcol = Bm + col0;

    // prologue: tile 0
    {
        float4 a0 = *(const float4*)(Arow + ak);
        float4 b0 = *(const float4*)(Bcol + (size_t)bk * N + bn4);
        As[0][ak + 0][am] = a0.x; As[0][ak + 1][am] = a0.y;
        As[0][ak + 2][am] = a0.z; As[0][ak + 3][am] = a0.w;
        *(float4*)&Bs[0][bk][bn4] = b0;
    }
    __syncthreads();

    float acc[8][8];
#pragma unroll
    for (int i = 0; i < 8; i++)
#pragma unroll
        for (int j = 0; j < 8; j++) acc[i][j] = 0.f;

    const int ty = tid >> 4, tx = tid & 15;
    int buf = 0;

#pragma unroll 1
    for (int kt = 0; kt < 32; kt++) {
        float4 nA, nB;
        if (kt < 31) {
            int k0 = (kt + 1) * 8;
            nA = *(const float4*)(Arow + k0 + ak);
            nB = *(const float4*)(Bcol + (size_t)(k0 + bk) * N + bn4);
        }
#pragma unroll
        for (int kk = 0; kk < 8; kk++) {
            float a[8], b[8];
            *(float4*)&a[0] = *(const float4*)&As[buf][kk][ty * 8];
            *(float4*)&a[4] = *(const float4*)&As[buf][kk][ty * 8 + 4];
            *(float4*)&b[0] = *(const float4*)&Bs[buf][kk][tx * 8];
            *(float4*)&b[4] = *(const float4*)&Bs[buf][kk][tx * 8 + 4];
#pragma unroll
            for (int i = 0; i < 8; i++)
#pragma unroll
                for (int j = 0; j < 8; j++) acc[i][j] += a[i] * b[j];
        }
        if (kt < 31) {
            buf ^= 1;
            As[buf][ak + 0][am] = nA.x; As[buf][ak + 1][am] = nA.y;
            As[buf][ak + 2][am] = nA.z; As[buf][ak + 3][am] = nA.w;
            *(float4*)&Bs[buf][bk][bn4] = nB;
            __syncthreads();
        }
    }

#pragma unroll
    for (int i = 0; i < 8; i++) {
        int r = row0 + ty * 8 + i;
#pragma unroll
        for (int j = 0; j < 8; j++) {
            int cidx = col0 + tx * 8 + j;
            float v = acc[i][j];
            if (MODE == 1) {
                if (cidx < 256) g_annprojT[cidx * 2048 + r] = v + bias0[cidx];
                else            g_annWi[(size_t)r * 768 + (cidx - 256)] = v;
            } else if (MODE == 2) {
                float bv = (cidx < 256) ? bias0[cidx]
                         : (cidx < 512) ? bias1[cidx - 256] : bias2[cidx - 512];
                g_xproj[(size_t)r * 768 + cidx] = v + bv;
            } else {
                Cout[(size_t)r * (size_t)N + cidx] = v + bias0[cidx];
            }
        }
    }
}

// ---------------------------------------------------------------------------
// K3: persistent recurrence. 128 CTAs x 256 threads, 2 grid barriers / step.
// Phase A: hcat = h @ Wcat (CTA c owns 8 of 1024 cols, weights SMEM-resident),
//          CTAs 0..31 also emit partial attention logits over their 8 h-cols.
// Phase B: CTA (b, dslice): sum partial logits -> softmax -> gate sums over
//          precomputed annWi/xproj -> GRU update -> h_new, hiddens, attentions.
// ---------------------------------------------------------------------------
__global__ void __launch_bounds__(256, 1)
recurrence_kernel(const float* __restrict__ hidden_init,
                  const float* __restrict__ W2,
                  float* __restrict__ att_out) {
    __shared__ __align__(16) float hs[32 * 256];  // 32 KB
    __shared__ float wsA[256 * 8];                // 8 KB persistent weight slice
    __shared__ float bsA[8];
    __shared__ float W2s[256];
    __shared__ float qs[32 * 8];
    __shared__ float us[64];
    __shared__ float red0;

    const int c = blockIdx.x, tid = threadIdx.x;

    for (int i = tid; i < 256 * 8; i += 256) {
        int k = i >> 3, j = i & 7;
        wsA[i] = g_Wcat[k * 1024 + c * 8 + j];
    }
    if (tid < 8) bsA[tid] = g_bcat[c * 8 + tid];
    W2s[tid] = W2[tid];

    // init h state (each replay)
    {
        int i = c * 256 + tid;
        if (i < 32 * 256) g_hbuf[i] = hidden_init[i];
    }
    grid_barrier();

    const int myb = c >> 2, myds = c & 3;

    for (int t = 0; t < TT; t++) {
        // ---- Phase A ----
        for (int i = tid * 4; i < 32 * 256; i += 1024)
            *(float4*)(hs + i) = *(const float4*)(g_hbuf + i);
        __syncthreads();
        {
            int b = tid >> 3, j = tid & 7;
            float a = bsA[j];
            const float* hp = &hs[b * 256];
#pragma unroll 8
            for (int k = 0; k < 256; k++) a += hp[k] * wsA[k * 8 + j];
            g_hcat[b * 1024 + c * 8 + j] = a;
            if (c < 32) qs[b * 8 + j] = a;  // qproj cols (bias 0)
        }
        if (c < 32) {
            __syncthreads();
#pragma unroll
            for (int rep = 0; rep < 8; rep++) {
                int bs = rep * 256 + tid;
                int b = bs >> 6;
                float a = 0.f;
#pragma unroll
                for (int j = 0; j < 8; j++) {
                    int col = c * 8 + j;
                    float v = qs[b * 8 + j] + g_annprojT[col * 2048 + bs];
                    a += W2s[col] * fmaxf(v, 0.f);
                }
                g_upart[c * 2048 + bs] = a;
            }
        }
        grid_barrier();

        // ---- Phase B ----
        if (tid < 64) {
            float u = 0.f;
#pragma unroll 8
            for (int cc = 0; cc < 32; cc++) u += g_upart[cc * 2048 + myb * 64 + tid];
            us[tid] = u;
        }
        __syncthreads();
        if (tid == 0) {
            float m = us[0];
            for (int s = 1; s < 64; s++) m = fmaxf(m, us[s]);
            float sum = 0.f;
            for (int s = 0; s < 64; s++) { float e = __expf(us[s] - m); us[s] = e; sum += e; }
            red0 = 1.f / sum;
        }
        __syncthreads();
        if (tid < 64) us[tid] *= red0;
        __syncthreads();
        if (myds == 0 && tid < 64)
            att_out[(myb * SS + tid) * TT + t] = us[tid];
        if (tid < 64) {
            int d = myds * 64 + tid;
            float az = 0.f, ar = 0.f, ah = 0.f;
            const float* aW = g_annWi + (size_t)myb * 64 * 768;
#pragma unroll 4
            for (int s = 0; s < 64; s++) {
                float w = us[s];
                const float* rowp = aW + s * 768;
                az += w * rowp[d];
                ar += w * rowp[256 + d];
                ah += w * rowp[512 + d];
            }
            const float* xp = g_xproj + (size_t)(t * 32 + myb) * 768;
            const float* hc = g_hcat + myb * 1024;
            float z = 1.f / (1.f + __expf(-(az + xp[d] + hc[256 + d])));
            float r = 1.f / (1.f + __expf(-(ar + xp[256 + d] + hc[512 + d])));
            float g = tanhf(ah + xp[512 + d] + r * hc[768 + d]);
            float hold = g_hbuf[myb * 256 + d];
            float hn = (1.f - z) * g + z * hold;
            g_hbuf[myb * 256 + d] = hn;
            g_hiddens[(size_t)(myb * TT + t) * 256 + d] = hn;
        }
        grid_barrier();
    }
}

// ---------------------------------------------------------------------------
extern "C" void kernel_launch(void* const* d_in, const int* in_sizes, int n_in,
                              void* d_out, int out_size) {
    const int*   inputs = (const int*)  d_in[0];
    const float* ann    = (const float*)d_in[1];
    const float* hinit  = (const float*)d_in[2];
    const float* emb    = (const float*)d_in[3];
    const float* W1     = (const float*)d_in[4];
    const float* b1     = (const float*)d_in[5];
    const float* W2     = (const float*)d_in[6];
    /* b2 (d_in[7]) cancels in softmax */
    const float* Wiz    = (const float*)d_in[8];
    const float* biz    = (const float*)d_in[9];
    const float* Wir    = (const float*)d_in[10];
    const float* bir    = (const float*)d_in[11];
    const float* Wih    = (const float*)d_in[12];
    const float* bih    = (const float*)d_in[13];
    const float* Whz    = (const float*)d_in[14];
    const float* bhz    = (const float*)d_in[15];
    const float* Whr    = (const float*)d_in[16];
    const float* bhr    = (const float*)d_in[17];
    const float* Whh    = (const float*)d_in[18];
    const float* bhh    = (const float*)d_in[19];
    const float* Wout   = (const float*)d_in[20];
    const float* bout   = (const float*)d_in[21];

    float* out = (float*)d_out;
    float* att = out + (size_t)BB * TT * VV;

    prep_kernel<<<256, 256>>>(W1, Wiz, Wir, Wih, Whz, bhz, Whr, bhr, Whh, bhh);
    sgemm_k<1><<<dim3(16, 8), 256>>>(ann, nullptr, b1, nullptr, nullptr,
                                     nullptr, nullptr, nullptr, 1024);
    sgemm_k<2><<<dim3(16, 6), 256>>>(nullptr, nullptr, biz, bir, bih,
                                     nullptr, inputs, emb, 768);
    recurrence_kernel<<<NBLK, 256>>>(hinit, W2, att);
    sgemm_k<4><<<dim3(16, 250), 256>>>(nullptr, Wout, bout, nullptr, nullptr,
                                       out, nullptr, nullptr, VV);
}

// round 3
// speedup vs baseline: 1.6101x; 1.6101x over previous
#include <cuda_runtime.h>
#include <cuda_bf16.h>
#include <cstdint>

// Problem constants
#define BB   32
#define TT   64
#define SS   64
#define HH   256
#define VV   32000
#define NBLK 128   // persistent recurrence grid

// ---------------------------------------------------------------------------
// PTX helpers (plain sm_103 feature set only: cp.async, ldmatrix, mma.sync)
// ---------------------------------------------------------------------------
__device__ __forceinline__ uint32_t smem_u32(const void* p) {
    uint32_t a;
    asm("{ .reg .u64 t; cvta.to.shared.u64 t, %1; cvt.u32.u64 %0, t; }" : "=r"(a) : "l"(p));
    return a;
}
__device__ __forceinline__ void cp_async16(uint32_t dst, const void* src) {
    asm volatile("cp.async.cg.shared.global [%0], [%1], 16;" :: "r"(dst), "l"(src));
}
#define CP_COMMIT() asm volatile("cp.async.commit_group;" ::: "memory")
#define CP_WAIT(n)  asm volatile("cp.async.wait_group %0;" :: "n"(n) : "memory")

__device__ __forceinline__ void ldsm_x4(uint32_t addr, uint32_t& r0, uint32_t& r1,
                                        uint32_t& r2, uint32_t& r3) {
    asm volatile("ldmatrix.sync.aligned.m8n8.x4.shared.b16 {%0,%1,%2,%3}, [%4];"
                 : "=r"(r0), "=r"(r1), "=r"(r2), "=r"(r3) : "r"(addr));
}
__device__ __forceinline__ void mma16816(float* c, const uint32_t* a,
                                         uint32_t b0, uint32_t b1) {
    asm volatile("mma.sync.aligned.m16n8k16.row.col.f32.bf16.bf16.f32 "
                 "{%0,%1,%2,%3}, {%4,%5,%6,%7}, {%8,%9}, {%0,%1,%2,%3};"
                 : "+f"(c[0]), "+f"(c[1]), "+f"(c[2]), "+f"(c[3])
                 : "r"(a[0]), "r"(a[1]), "r"(a[2]), "r"(a[3]), "r"(b0), "r"(b1));
}

// ---------------------------------------------------------------------------
// Device scratch
// ---------------------------------------------------------------------------
__device__ __align__(16) float g_Wcat[256 * 1024];
__device__ __align__(16) float g_bcat[1024];
__device__ __align__(16) float g_Wann[256 * 1024];
__device__ __align__(16) float g_Wx[256 * 768];
__device__ __align__(16) float g_annprojT[256 * 2048];
__device__ __align__(16) float g_annWi[2048 * 768];
__device__ __align__(16) float g_xproj[2048 * 768];
__device__ __align__(16) float g_hcat[32 * 1024];
__device__ __align__(16) float g_upart[32 * 2048];
__device__ __align__(16) float g_hbuf[32 * 256];
__device__ __align__(16) __nv_bfloat16 g_Abig[2048 * 768];   // [A_hi | A_lo | A_hi]
__device__ __align__(16) __nv_bfloat16 g_Bbig[32000L * 768]; // [B_hi | B_hi | B_lo]

__device__ unsigned g_bar_count;
__device__ volatile unsigned g_bar_gen;

// ---------------------------------------------------------------------------
__device__ __forceinline__ void grid_barrier() {
    __syncthreads();
    if (threadIdx.x == 0) {
        unsigned gen = g_bar_gen;
        __threadfence();
        if (atomicAdd(&g_bar_count, 1u) == NBLK - 1) {
            atomicExch(&g_bar_count, 0u);
            __threadfence();
            g_bar_gen = gen + 1;
        } else {
            while (g_bar_gen == gen) { }
            __threadfence();
        }
    }
    __syncthreads();
}

// ---------------------------------------------------------------------------
// K0: build fused weight matrices
// ---------------------------------------------------------------------------
__global__ void prep_kernel(const float* __restrict__ W1,
                            const float* __restrict__ Wiz, const float* __restrict__ Wir,
                            const float* __restrict__ Wih,
                            const float* __restrict__ Whz, const float* __restrict__ bhz,
                            const float* __restrict__ Whr, const float* __restrict__ bhr,
                            const float* __restrict__ Whh, const float* __restrict__ bhh) {
    int idx = blockIdx.x * blockDim.x + threadIdx.x;
    int stride = gridDim.x * blockDim.x;
    for (int i = idx; i < 256 * 1024; i += stride) {
        int k = i >> 10, j = i & 1023;
        float wc, wa;
        if (j < 256)      { wc = W1[k * 256 + j];          wa = W1[(256 + k) * 256 + j]; }
        else if (j < 512) { wc = Whz[k * 256 + j - 256];   wa = Wiz[k * 256 + j - 256]; }
        else if (j < 768) { wc = Whr[k * 256 + j - 512];   wa = Wir[k * 256 + j - 512]; }
        else              { wc = Whh[k * 256 + j - 768];   wa = Wih[k * 256 + j - 768]; }
        g_Wcat[i] = wc; g_Wann[i] = wa;
    }
    for (int i = idx; i < 256 * 768; i += stride) {
        int k = i / 768, j = i % 768;
        float w;
        if (j < 256)      w = Wiz[(256 + k) * 256 + j];
        else if (j < 512) w = Wir[(256 + k) * 256 + j - 256];
        else              w = Wih[(256 + k) * 256 + j - 512];
        g_Wx[i] = w;
    }
    for (int i = idx; i < 1024; i += stride) {
        float bv = 0.f;
        if (i >= 256 && i < 512)      bv = bhz[i - 256];
        else if (i >= 512 && i < 768) bv = bhr[i - 512];
        else if (i >= 768)            bv = bhh[i - 768];
        g_bcat[i] = bv;
    }
}

// ---------------------------------------------------------------------------
// K0b: Wout (K=256 x V) -> Bbig[n][768] bf16 K-major: [hi(256) | hi(256) | lo(256)]
// ---------------------------------------------------------------------------
__global__ void __launch_bounds__(256)
bprep_kernel(const float* __restrict__ Wout) {
    __shared__ float sw[32][132];
    const int tid = threadIdx.x;
    const int k0 = blockIdx.x * 32, n0 = blockIdx.y * 128;
    for (int i = tid; i < 32 * 128; i += 256) {
        int k = i >> 7, n = i & 127;
        sw[k][n] = Wout[(size_t)(k0 + k) * VV + n0 + n];
    }
    __syncthreads();
    const int n = tid >> 1;
    const bool lo = tid & 1;
    __align__(16) __nv_bfloat16 vals[32];
#pragma unroll
    for (int k = 0; k < 32; k++) {
        float w = sw[k][n];
        __nv_bfloat16 h = __float2bfloat16(w);
        vals[k] = lo ? __float2bfloat16(w - __bfloat162float(h)) : h;
    }
    __nv_bfloat16* dst = g_Bbig + (size_t)(n0 + n) * 768;
    const uint4* v4 = (const uint4*)vals;
#pragma unroll
    for (int u = 0; u < 4; u++) {
        if (!lo) {
            *(uint4*)(dst + k0 + u * 8)       = v4[u];
            *(uint4*)(dst + 256 + k0 + u * 8) = v4[u];
        } else {
            *(uint4*)(dst + 512 + k0 + u * 8) = v4[u];
        }
    }
}

// ---------------------------------------------------------------------------
// Small fp32 SGEMMs (modes 1,2)
// ---------------------------------------------------------------------------
template <int MODE>
__global__ void __launch_bounds__(256, 2)
sgemm_k(const float* __restrict__ Aarg,
        const float* __restrict__ bias0, const float* __restrict__ bias1,
        const float* __restrict__ bias2,
        const int* __restrict__ tok_inputs, const float* __restrict__ emb, int N) {
    __shared__ __align__(16) float As[2][8][128];
    __shared__ __align__(16) float Bs[2][8][128];
    __shared__ int tok[128];

    const int tid = threadIdx.x;
    const int row0 = blockIdx.x * 128;
    const int col0 = blockIdx.y * 128;

    if (MODE == 2) {
        if (tid < 128) {
            int r = row0 + tid;
            int t = r >> 5, b = r & 31;
            tok[tid] = tok_inputs[b * TT + t];
        }
        __syncthreads();
    }

    const float* Bm = (MODE == 1) ? g_Wann : g_Wx;
    const int am  = tid >> 1;
    const int ak  = (tid & 1) * 4;
    const int bk  = tid >> 5;
    const int bn4 = (tid & 31) * 4;

    const float* Arow = (MODE == 2) ? (emb + (size_t)tok[am] * 256)
                                    : (Aarg + (size_t)(row0 + am) * 256);
    const float* Bcol = Bm + col0;

    {
        float4 a0 = *(const float4*)(Arow + ak);
        float4 b0 = *(const float4*)(Bcol + (size_t)bk * N + bn4);
        As[0][ak + 0][am] = a0.x; As[0][ak + 1][am] = a0.y;
        As[0][ak + 2][am] = a0.z; As[0][ak + 3][am] = a0.w;
        *(float4*)&Bs[0][bk][bn4] = b0;
    }
    __syncthreads();

    float acc[8][8];
#pragma unroll
    for (int i = 0; i < 8; i++)
#pragma unroll
        for (int j = 0; j < 8; j++) acc[i][j] = 0.f;

    const int ty = tid >> 4, tx = tid & 15;
    int buf = 0;

#pragma unroll 1
    for (int kt = 0; kt < 32; kt++) {
        float4 nA, nB;
        if (kt < 31) {
            int k0 = (kt + 1) * 8;
            nA = *(const float4*)(Arow + k0 + ak);
            nB = *(const float4*)(Bcol + (size_t)(k0 + bk) * N + bn4);
        }
#pragma unroll
        for (int kk = 0; kk < 8; kk++) {
            float a[8], b[8];
            *(float4*)&a[0] = *(const float4*)&As[buf][kk][ty * 8];
            *(float4*)&a[4] = *(const float4*)&As[buf][kk][ty * 8 + 4];
            *(float4*)&b[0] = *(const float4*)&Bs[buf][kk][tx * 8];
            *(float4*)&b[4] = *(const float4*)&Bs[buf][kk][tx * 8 + 4];
#pragma unroll
            for (int i = 0; i < 8; i++)
#pragma unroll
                for (int j = 0; j < 8; j++) acc[i][j] += a[i] * b[j];
        }
        if (kt < 31) {
            buf ^= 1;
            As[buf][ak + 0][am] = nA.x; As[buf][ak + 1][am] = nA.y;
            As[buf][ak + 2][am] = nA.z; As[buf][ak + 3][am] = nA.w;
            *(float4*)&Bs[buf][bk][bn4] = nB;
            __syncthreads();
        }
    }

#pragma unroll
    for (int i = 0; i < 8; i++) {
        int r = row0 + ty * 8 + i;
#pragma unroll
        for (int j = 0; j < 8; j++) {
            int cidx = col0 + tx * 8 + j;
            float v = acc[i][j];
            if (MODE == 1) {
                if (cidx < 256) g_annprojT[cidx * 2048 + r] = v + bias0[cidx];
                else            g_annWi[(size_t)r * 768 + (cidx - 256)] = v;
            } else {
                float bv = (cidx < 256) ? bias0[cidx]
                         : (cidx < 512) ? bias1[cidx - 256] : bias2[cidx - 512];
                g_xproj[(size_t)r * 768 + cidx] = v + bv;
            }
        }
    }
}

// ---------------------------------------------------------------------------
// K3: persistent recurrence (vectorized phase A, parallel phase B)
// ---------------------------------------------------------------------------
__global__ void __launch_bounds__(256, 1)
recurrence_kernel(const float* __restrict__ hidden_init,
                  const float* __restrict__ W2,
                  float* __restrict__ att_out) {
    __shared__ __align__(16) float hs[32 * 260];
    __shared__ __align__(16) float wsT[8 * 260];
    __shared__ float bsA[8];
    __shared__ float W2s[256];
    __shared__ float qs[32 * 8];
    __shared__ float usraw[64];
    __shared__ float us[64];
    __shared__ float gz[64], gr[64], gh[64];

    const int c = blockIdx.x, tid = threadIdx.x;

    for (int i = tid; i < 2048; i += 256) {
        int j = i >> 8, k = i & 255;
        wsT[j * 260 + k] = g_Wcat[k * 1024 + c * 8 + j];
    }
    if (tid < 8) bsA[tid] = g_bcat[c * 8 + tid];
    W2s[tid] = W2[tid];
    { int i = c * 256 + tid; if (i < 32 * 256) g_hbuf[i] = hidden_init[i]; }
    grid_barrier();

    const int myb = c >> 2, myds = c & 3;
    const int bA = tid >> 3, jA = tid & 7;

    for (int t = 0; t < TT; t++) {
        // ---- Phase A ----
        for (int i = tid * 4; i < 32 * 256; i += 1024) {
            float4 v = *(const float4*)(g_hbuf + i);
            *(float4*)&hs[(i >> 8) * 260 + (i & 255)] = v;
        }
        __syncthreads();
        {
            float a = bsA[jA];
            const float* hp = &hs[bA * 260];
            const float* wp = &wsT[jA * 260];
#pragma unroll
            for (int k = 0; k < 256; k += 4) {
                float4 hv = *(const float4*)(hp + k);
                float4 wv = *(const float4*)(wp + k);
                a += hv.x * wv.x + hv.y * wv.y + hv.z * wv.z + hv.w * wv.w;
            }
            g_hcat[bA * 1024 + c * 8 + jA] = a;
            if (c < 32) qs[bA * 8 + jA] = a;
        }
        if (c < 32) {
            __syncthreads();
#pragma unroll
            for (int rep = 0; rep < 8; rep++) {
                int bs = rep * 256 + tid;
                int b = bs >> 6;
                float a = 0.f;
#pragma unroll
                for (int j = 0; j < 8; j++) {
                    int col = c * 8 + j;
                    float v = qs[b * 8 + j] + g_annprojT[col * 2048 + bs];
                    a += W2s[col] * fmaxf(v, 0.f);
                }
                g_upart[c * 2048 + bs] = a;
            }
        }
        grid_barrier();

        // ---- Phase B ----
        if (tid < 64) {
            float u = 0.f;
#pragma unroll 8
            for (int cc = 0; cc < 32; cc++) u += g_upart[cc * 2048 + myb * 64 + tid];
            usraw[tid] = u;
        }
        __syncthreads();
        if (tid < 32) {
            float v0 = usraw[tid], v1 = usraw[tid + 32];
            float m = fmaxf(v0, v1);
#pragma unroll
            for (int o = 16; o; o >>= 1) m = fmaxf(m, __shfl_xor_sync(0xffffffffu, m, o));
            float e0 = __expf(v0 - m), e1 = __expf(v1 - m);
            float ssum = e0 + e1;
#pragma unroll
            for (int o = 16; o; o >>= 1) ssum += __shfl_xor_sync(0xffffffffu, ssum, o);
            float inv = 1.f / ssum;
            us[tid] = e0 * inv; us[tid + 32] = e1 * inv;
        }
        __syncthreads();
        if (myds == 0 && tid < 64)
            att_out[(myb * SS + tid) * TT + t] = us[tid];
        if (tid < 192) {
            int g = tid >> 6, dd = tid & 63;
            const float* colp = g_annWi + (size_t)(myb * 64) * 768 + g * 256 + myds * 64 + dd;
            float acc = 0.f;
#pragma unroll 16
            for (int s = 0; s < 64; s++) acc += us[s] * colp[(size_t)s * 768];
            (g == 0 ? gz : g == 1 ? gr : gh)[dd] = acc;
        }
        __syncthreads();
        if (tid < 64) {
            int d = myds * 64 + tid;
            const float* xp = g_xproj + (size_t)(t * 32 + myb) * 768;
            const float* hc = g_hcat + myb * 1024;
            float z  = 1.f / (1.f + __expf(-(gz[tid] + xp[d]       + hc[256 + d])));
            float r  = 1.f / (1.f + __expf(-(gr[tid] + xp[256 + d] + hc[512 + d])));
            float g2 = tanhf(gh[tid] + xp[512 + d] + r * hc[768 + d]);
            float hold = g_hbuf[myb * 256 + d];
            float hn = (1.f - z) * g2 + z * hold;
            g_hbuf[myb * 256 + d] = hn;
            __nv_bfloat16 hi = __float2bfloat16(hn);
            __nv_bfloat16 lo = __float2bfloat16(hn - __bfloat162float(hi));
            size_t rb = (size_t)(myb * 64 + t) * 768;
            g_Abig[rb + d]       = hi;
            g_Abig[rb + 256 + d] = lo;
            g_Abig[rb + 512 + d] = hi;
        }
        grid_barrier();
    }
}

// ---------------------------------------------------------------------------
// K4: HMMA bf16 GEMM  D[2048,32000] = Abig[2048,768] @ Bbig[32000,768]^T
// tile 128x128, BK=32, 3-stage cp.async pipeline, 8 warps x (64x32)
// SMEM swizzle: 16B chunk col ^= (row>>1)&3  (conflict-free LDGSTS + LDSM)
// ---------------------------------------------------------------------------
#define GSTAGES 3

__global__ void __launch_bounds__(256, 2)
gemm_mma_kernel(const float* __restrict__ bout, float* __restrict__ out) {
    __shared__ __align__(128) __nv_bfloat16 sA[GSTAGES][128 * 32];
    __shared__ __align__(128) __nv_bfloat16 sB[GSTAGES][128 * 32];

    const int tid  = threadIdx.x;
    const int lane = tid & 31, wid = tid >> 5;
    const int wr = wid >> 2, wc = wid & 3;     // warp grid 2 x 4
    const int row0 = blockIdx.x * 128, col0 = blockIdx.y * 128;

    const __nv_bfloat16* Ag = g_Abig + (size_t)row0 * 768;
    const __nv_bfloat16* Bg = g_Bbig + (size_t)col0 * 768;

    const uint32_t sAb = smem_u32(sA);
    const uint32_t sBb = smem_u32(sB);

    // cp.async: 512 16B-chunks per tile per stage; thread handles chunks tid, tid+256
    const int rA0 = tid >> 2,          cA0 = tid & 3;
    const int rA1 = (tid + 256) >> 2,  cA1 = tid & 3;
    const uint32_t dA0 = rA0 * 64 + ((cA0 ^ ((rA0 >> 1) & 3)) * 16);
    const uint32_t dA1 = rA1 * 64 + ((cA1 ^ ((rA1 >> 1) & 3)) * 16);

#define LOAD_STAGE(s, kt) do {                                                  \
        uint32_t ab = sAb + (s) * 8192, bb = sBb + (s) * 8192;                  \
        cp_async16(ab + dA0, Ag + (size_t)rA0 * 768 + (kt) * 32 + cA0 * 8);     \
        cp_async16(ab + dA1, Ag + (size_t)rA1 * 768 + (kt) * 32 + cA1 * 8);     \
        cp_async16(bb + dA0, Bg + (size_t)rA0 * 768 + (kt) * 32 + cA0 * 8);     \
        cp_async16(bb + dA1, Bg + (size_t)rA1 * 768 + (kt) * 32 + cA1 * 8);     \
    } while (0)

    LOAD_STAGE(0, 0); CP_COMMIT();
    LOAD_STAGE(1, 1); CP_COMMIT();

    float acc[4][4][4];
#pragma unroll
    for (int i = 0; i < 4; i++)
#pragma unroll
        for (int j = 0; j < 4; j++)
#pragma unroll
            for (int q = 0; q < 4; q++) acc[i][j][q] = 0.f;

    // ldmatrix lane address components
    const int aRow = lane & 15;           // row within 16
    const int aSel = lane >> 4;           // 0/1 -> k8 half
    const int bRow = (lane & 7) + ((lane >> 4) << 3);  // n row within 16
    const int bSel = (lane >> 3) & 1;     // k8 half

#pragma unroll 1
    for (int kt = 0; kt < 24; kt++) {
        CP_WAIT(1);
        __syncthreads();
        if (kt + 2 < 24) LOAD_STAGE((kt + 2) % GSTAGES, kt + 2);
        CP_COMMIT();

        const int st = kt % GSTAGES;
        const uint32_t ab = sAb + st * 8192;
        const uint32_t bb = sBb + st * 8192;

#pragma unroll
        for (int kf = 0; kf < 2; kf++) {
            uint32_t aF[4][4];
#pragma unroll
            for (int mf = 0; mf < 4; mf++) {
                int row = wr * 64 + mf * 16 + aRow;
                int ch  = (kf * 2 + aSel) ^ ((row >> 1) & 3);
                ldsm_x4(ab + row * 64 + ch * 16, aF[mf][0], aF[mf][1], aF[mf][2], aF[mf][3]);
            }
            uint32_t bF[2][4];
#pragma unroll
            for (int nf2 = 0; nf2 < 2; nf2++) {
                int row = wc * 32 + nf2 * 16 + bRow;
                int ch  = (kf * 2 + bSel) ^ ((row >> 1) & 3);
                ldsm_x4(bb + row * 64 + ch * 16, bF[nf2][0], bF[nf2][1], bF[nf2][2], bF[nf2][3]);
            }
#pragma unroll
            for (int mf = 0; mf < 4; mf++)
#pragma unroll
                for (int nf = 0; nf < 4; nf++) {
                    uint32_t b0 = bF[nf >> 1][(nf & 1) * 2 + 0];
                    uint32_t b1 = bF[nf >> 1][(nf & 1) * 2 + 1];
                    mma16816(acc[mf][nf], aF[mf], b0, b1);
                }
        }
        __syncthreads();
    }

    // epilogue: direct float2 stores + bias
    const int rq = lane >> 2, cq = (lane & 3) * 2;
    const int rbase = row0 + wr * 64, cbase = col0 + wc * 32;
#pragma unroll
    for (int mf = 0; mf < 4; mf++) {
#pragma unroll
        for (int nf = 0; nf < 4; nf++) {
            int r  = rbase + mf * 16 + rq;
            int cc = cbase + nf * 8 + cq;
            float bz0 = bout[cc], bz1 = bout[cc + 1];
            float2 v0 = make_float2(acc[mf][nf][0] + bz0, acc[mf][nf][1] + bz1);
            float2 v1 = make_float2(acc[mf][nf][2] + bz0, acc[mf][nf][3] + bz1);
            *(float2*)&out[(size_t)r * VV + cc]       = v0;
            *(float2*)&out[(size_t)(r + 8) * VV + cc] = v1;
        }
    }
#undef LOAD_STAGE
}

// ---------------------------------------------------------------------------
extern "C" void kernel_launch(void* const* d_in, const int* in_sizes, int n_in,
                              void* d_out, int out_size) {
    const int*   inputs = (const int*)  d_in[0];
    const float* ann    = (const float*)d_in[1];
    const float* hinit  = (const float*)d_in[2];
    const float* emb    = (const float*)d_in[3];
    const float* W1     = (const float*)d_in[4];
    const float* b1     = (const float*)d_in[5];
    const float* W2     = (const float*)d_in[6];
    /* b2 (d_in[7]) cancels in softmax */
    const float* Wiz    = (const float*)d_in[8];
    const float* biz    = (const float*)d_in[9];
    const float* Wir    = (const float*)d_in[10];
    const float* bir    = (const float*)d_in[11];
    const float* Wih    = (const float*)d_in[12];
    const float* bih    = (const float*)d_in[13];
    const float* Whz    = (const float*)d_in[14];
    const float* bhz    = (const float*)d_in[15];
    const float* Whr    = (const float*)d_in[16];
    const float* bhr    = (const float*)d_in[17];
    const float* Whh    = (const float*)d_in[18];
    const float* bhh    = (const float*)d_in[19];
    const float* Wout   = (const float*)d_in[20];
    const float* bout   = (const float*)d_in[21];

    float* out = (float*)d_out;
    float* att = out + (size_t)BB * TT * VV;

    prep_kernel<<<256, 256>>>(W1, Wiz, Wir, Wih, Whz, bhz, Whr, bhr, Whh, bhh);
    bprep_kernel<<<dim3(8, 250), 256>>>(Wout);
    sgemm_k<1><<<dim3(16, 8), 256>>>(ann, b1, nullptr, nullptr, nullptr, nullptr, 1024);
    sgemm_k<2><<<dim3(16, 6), 256>>>(nullptr, biz, bir, bih, inputs, emb, 768);
    recurrence_kernel<<<NBLK, 256>>>(hinit, W2, att);
    gemm_mma_kernel<<<dim3(16, 250), 256>>>(bout, out);
}

// round 4
// speedup vs baseline: 1.9169x; 1.1906x over previous
#include <cuda_runtime.h>
#include <cuda_fp16.h>
#include <cstdint>

// Problem constants
#define BB   32
#define TT   64
#define SS   64
#define HH   256
#define VV   32000
#define NBLK 128   // persistent recurrence grid

// ---------------------------------------------------------------------------
// PTX helpers (plain sm_103 feature set: cp.async, ldmatrix, mma.sync)
// ---------------------------------------------------------------------------
__device__ __forceinline__ uint32_t smem_u32(const void* p) {
    uint32_t a;
    asm("{ .reg .u64 t; cvta.to.shared.u64 t, %1; cvt.u32.u64 %0, t; }" : "=r"(a) : "l"(p));
    return a;
}
__device__ __forceinline__ void cp_async16(uint32_t dst, const void* src) {
    asm volatile("cp.async.cg.shared.global [%0], [%1], 16;" :: "r"(dst), "l"(src));
}
#define CP_COMMIT() asm volatile("cp.async.commit_group;" ::: "memory")
#define CP_WAIT(n)  asm volatile("cp.async.wait_group %0;" :: "n"(n) : "memory")

__device__ __forceinline__ void ldsm_x4(uint32_t addr, uint32_t& r0, uint32_t& r1,
                                        uint32_t& r2, uint32_t& r3) {
    asm volatile("ldmatrix.sync.aligned.m8n8.x4.shared.b16 {%0,%1,%2,%3}, [%4];"
                 : "=r"(r0), "=r"(r1), "=r"(r2), "=r"(r3) : "r"(addr));
}
__device__ __forceinline__ void mma16816(float* c, const uint32_t* a,
                                         uint32_t b0, uint32_t b1) {
    asm volatile("mma.sync.aligned.m16n8k16.row.col.f32.f16.f16.f32 "
                 "{%0,%1,%2,%3}, {%4,%5,%6,%7}, {%8,%9}, {%0,%1,%2,%3};"
                 : "+f"(c[0]), "+f"(c[1]), "+f"(c[2]), "+f"(c[3])
                 : "r"(a[0]), "r"(a[1]), "r"(a[2]), "r"(a[3]), "r"(b0), "r"(b1));
}

// ---------------------------------------------------------------------------
// Device scratch
// ---------------------------------------------------------------------------
__device__ __align__(16) float g_Wcat[256 * 1024];
__device__ __align__(16) float g_bcat[1024];
__device__ __align__(16) float g_Wann[256 * 1024];
__device__ __align__(16) float g_Wx[256 * 768];
__device__ __align__(16) float g_annprojT[256 * 2048];
__device__ __align__(16) float g_annWi[2048 * 768];
__device__ __align__(16) float g_xproj[2048 * 768];
__device__ __align__(16) float g_hcat[32 * 1024];
__device__ __align__(16) float g_upart[32 * 2048];
__device__ __align__(16) float g_hbuf[32 * 256];
__device__ __align__(16) __half g_Ah[2048 * 512];    // [A_hi(256) | A_lo(256)] per row
__device__ __align__(16) __half g_Bh[32000L * 256];  // B_hi only, K-major

__device__ unsigned g_bar_count;
__device__ volatile unsigned g_bar_gen;

// ---------------------------------------------------------------------------
__device__ __forceinline__ void grid_barrier() {
    __syncthreads();
    if (threadIdx.x == 0) {
        unsigned gen = g_bar_gen;
        __threadfence();
        if (atomicAdd(&g_bar_count, 1u) == NBLK - 1) {
            atomicExch(&g_bar_count, 0u);
            __threadfence();
            g_bar_gen = gen + 1;
        } else {
            while (g_bar_gen == gen) { }
            __threadfence();
        }
    }
    __syncthreads();
}

// ---------------------------------------------------------------------------
// K0: build fused weight matrices
// ---------------------------------------------------------------------------
__global__ void prep_kernel(const float* __restrict__ W1,
                            const float* __restrict__ Wiz, const float* __restrict__ Wir,
                            const float* __restrict__ Wih,
                            const float* __restrict__ Whz, const float* __restrict__ bhz,
                            const float* __restrict__ Whr, const float* __restrict__ bhr,
                            const float* __restrict__ Whh, const float* __restrict__ bhh) {
    int idx = blockIdx.x * blockDim.x + threadIdx.x;
    int stride = gridDim.x * blockDim.x;
    for (int i = idx; i < 256 * 1024; i += stride) {
        int k = i >> 10, j = i & 1023;
        float wc, wa;
        if (j < 256)      { wc = W1[k * 256 + j];          wa = W1[(256 + k) * 256 + j]; }
        else if (j < 512) { wc = Whz[k * 256 + j - 256];   wa = Wiz[k * 256 + j - 256]; }
        else if (j < 768) { wc = Whr[k * 256 + j - 512];   wa = Wir[k * 256 + j - 512]; }
        else              { wc = Whh[k * 256 + j - 768];   wa = Wih[k * 256 + j - 768]; }
        g_Wcat[i] = wc; g_Wann[i] = wa;
    }
    for (int i = idx; i < 256 * 768; i += stride) {
        int k = i / 768, j = i % 768;
        float w;
        if (j < 256)      w = Wiz[(256 + k) * 256 + j];
        else if (j < 512) w = Wir[(256 + k) * 256 + j - 256];
        else              w = Wih[(256 + k) * 256 + j - 512];
        g_Wx[i] = w;
    }
    for (int i = idx; i < 1024; i += stride) {
        float bv = 0.f;
        if (i >= 256 && i < 512)      bv = bhz[i - 256];
        else if (i >= 512 && i < 768) bv = bhr[i - 512];
        else if (i >= 768)            bv = bhh[i - 768];
        g_bcat[i] = bv;
    }
}

// ---------------------------------------------------------------------------
// K1 combo: one launch = sgemm mode1 (512 CTAs) + sgemm mode2 (384) + Wout->fp16 (4000)
// sgemm: 64x64 tile, BK=16, 128 threads, 4x8 microtile, double-buffered
// ---------------------------------------------------------------------------
__global__ void __launch_bounds__(128)
combo_kernel(const float* __restrict__ ann, const float* __restrict__ emb,
             const int* __restrict__ inputs, const float* __restrict__ Wout,
             const float* __restrict__ b1, const float* __restrict__ biz,
             const float* __restrict__ bir, const float* __restrict__ bih) {
    __shared__ __align__(16) float sm[2][64 * 20 + 16 * 68];
    __shared__ __align__(16) float sw[32 * 68];
    __shared__ int tok[64];

    const int bid = blockIdx.x, tid = threadIdx.x;

    if (bid >= 896) {
        // ---- Wout -> g_Bh fp16 (transpose via smem) ----
        int b3 = bid - 896;
        int k0 = (b3 & 7) * 32, n0 = (b3 >> 3) * 64;
        for (int i = tid; i < 32 * 64; i += 128) {
            int k = i >> 6, n = i & 63;
            sw[k * 68 + n] = Wout[(size_t)(k0 + k) * VV + n0 + n];
        }
        __syncthreads();
        const int n = tid >> 1, kh = (tid & 1) * 16;
        __align__(16) __half vals[16];
#pragma unroll
        for (int j = 0; j < 16; j++) vals[j] = __float2half(sw[(kh + j) * 68 + n]);
        __half* dst = g_Bh + (size_t)(n0 + n) * 256 + k0 + kh;
        *(uint4*)dst       = ((const uint4*)vals)[0];
        *(uint4*)(dst + 8) = ((const uint4*)vals)[1];
        return;
    }

    // ---- small SGEMM: A(2048x256) @ B(256xN) ----
    const bool m1 = bid < 512;
    int row0, col0, N;
    const float* Bm;
    if (m1) { row0 = (bid >> 4) * 64; col0 = (bid & 15) * 64; N = 1024; Bm = g_Wann; }
    else    { int b2 = bid - 512; row0 = (b2 / 12) * 64; col0 = (b2 % 12) * 64; N = 768; Bm = g_Wx; }

    if (!m1 && tid < 64) {
        int r = row0 + tid;
        tok[tid] = inputs[(r & 31) * TT + (r >> 5)];
    }
    if (!m1) __syncthreads();

    const int rA = tid >> 2, kqA = (tid & 3) * 4;
    const int kB = tid >> 4, nB = (tid & 15) * 4;
    const float* ArowA = m1 ? (ann + (size_t)(row0 + rA) * 256)
                            : (emb + (size_t)tok[rA] * 256);
    const float* ArowB = m1 ? (ann + (size_t)(row0 + rA + 32) * 256)
                            : (emb + (size_t)tok[rA + 32] * 256);
    const float* Bcol = Bm + col0;

    // prologue tile 0
    {
        float4 a0 = *(const float4*)(ArowA + kqA);
        float4 a1 = *(const float4*)(ArowB + kqA);
        float4 b0 = *(const float4*)(Bcol + (size_t)kB * N + nB);
        float4 b1v = *(const float4*)(Bcol + (size_t)(kB + 8) * N + nB);
        *(float4*)&sm[0][rA * 20 + kqA]        = a0;
        *(float4*)&sm[0][(rA + 32) * 20 + kqA] = a1;
        *(float4*)&sm[0][1280 + kB * 68 + nB]        = b0;
        *(float4*)&sm[0][1280 + (kB + 8) * 68 + nB]  = b1v;
    }
    __syncthreads();

    float acc[4][8];
#pragma unroll
    for (int i = 0; i < 4; i++)
#pragma unroll
        for (int j = 0; j < 8; j++) acc[i][j] = 0.f;

    const int ty4 = (tid >> 3) * 4, tx8 = (tid & 7) * 8;
    int buf = 0;

#pragma unroll 1
    for (int kt = 0; kt < 16; kt++) {
        float4 nA0, nA1, nB0, nB1;
        if (kt < 15) {
            int k0 = (kt + 1) * 16;
            nA0 = *(const float4*)(ArowA + k0 + kqA);
            nA1 = *(const float4*)(ArowB + k0 + kqA);
            nB0 = *(const float4*)(Bcol + (size_t)(k0 + kB) * N + nB);
            nB1 = *(const float4*)(Bcol + (size_t)(k0 + kB + 8) * N + nB);
        }
        const float* As_ = &sm[buf][0];
        const float* Bs_ = &sm[buf][1280];
#pragma unroll
        for (int kk = 0; kk < 16; kk++) {
            float a[4], b[8];
#pragma unroll
            for (int i = 0; i < 4; i++) a[i] = As_[(ty4 + i) * 20 + kk];
            *(float4*)&b[0] = *(const float4*)&Bs_[kk * 68 + tx8];
            *(float4*)&b[4] = *(const float4*)&Bs_[kk * 68 + tx8 + 4];
#pragma unroll
            for (int i = 0; i < 4; i++)
#pragma unroll
                for (int j = 0; j < 8; j++) acc[i][j] += a[i] * b[j];
        }
        if (kt < 15) {
            buf ^= 1;
            __syncthreads();
            *(float4*)&sm[buf][rA * 20 + kqA]        = nA0;
            *(float4*)&sm[buf][(rA + 32) * 20 + kqA] = nA1;
            *(float4*)&sm[buf][1280 + kB * 68 + nB]        = nB0;
            *(float4*)&sm[buf][1280 + (kB + 8) * 68 + nB]  = nB1;
            __syncthreads();
        }
    }

#pragma unroll
    for (int i = 0; i < 4; i++) {
        int r = row0 + ty4 + i;
#pragma unroll
        for (int j = 0; j < 8; j++) {
            int cidx = col0 + tx8 + j;
            float v = acc[i][j];
            if (m1) {
                if (cidx < 256) g_annprojT[cidx * 2048 + r] = v + b1[cidx];
                else            g_annWi[(size_t)r * 768 + (cidx - 256)] = v;
            } else {
                float bv = (cidx < 256) ? biz[cidx]
                         : (cidx < 512) ? bir[cidx - 256] : bih[cidx - 512];
                g_xproj[(size_t)r * 768 + cidx] = v + bv;
            }
        }
    }
}

// ---------------------------------------------------------------------------
// K3: persistent recurrence; dynamic smem caches the attention slice
// dsm layout: hs[32*260] | wsT[8*260] | annp[8*2048]
// ---------------------------------------------------------------------------
#define REC_DSMEM ((32 * 260 + 8 * 260 + 8 * 2048) * 4)

__global__ void __launch_bounds__(256, 1)
recurrence_kernel(const float* __restrict__ hidden_init,
                  const float* __restrict__ W2,
                  float* __restrict__ att_out) {
    extern __shared__ __align__(16) float dsm[];
    float* hs   = dsm;               // 32 x 260
    float* wsT  = dsm + 32 * 260;    // 8 x 260
    float* annp = wsT + 8 * 260;     // 8 x 2048 (CTAs < 32 only)

    __shared__ float bsA[8];
    __shared__ float W2s[256];
    __shared__ float qs[32 * 8];
    __shared__ float usq[4][64];
    __shared__ float us[64];
    __shared__ float gz[64], gr[64], gh[64];

    const int c = blockIdx.x, tid = threadIdx.x;

    for (int i = tid; i < 2048; i += 256) {
        int j = i >> 8, k = i & 255;
        wsT[j * 260 + k] = g_Wcat[k * 1024 + c * 8 + j];
    }
    if (tid < 8) bsA[tid] = g_bcat[c * 8 + tid];
    W2s[tid] = W2[tid];
    { int i = c * 256 + tid; if (i < 32 * 256) g_hbuf[i] = hidden_init[i]; }
    if (c < 32) {
        const float* src = g_annprojT + c * 8 * 2048;
        for (int i = tid * 4; i < 8 * 2048; i += 1024)
            *(float4*)&annp[i] = *(const float4*)&src[i];
    }
    grid_barrier();

    const int myb = c >> 2, myds = c & 3;
    const int bA = tid >> 3, jA = tid & 7;

    for (int t = 0; t < TT; t++) {
        // ---- Phase A: hcat = h @ Wcat ----
        for (int i = tid * 4; i < 32 * 256; i += 1024) {
            float4 v = *(const float4*)(g_hbuf + i);
            *(float4*)&hs[(i >> 8) * 260 + (i & 255)] = v;
        }
        __syncthreads();
        {
            float a = bsA[jA];
            const float* hp = &hs[bA * 260];
            const float* wp = &wsT[jA * 260];
#pragma unroll
            for (int k = 0; k < 256; k += 4) {
                float4 hv = *(const float4*)(hp + k);
                float4 wv = *(const float4*)(wp + k);
                a += hv.x * wv.x + hv.y * wv.y + hv.z * wv.z + hv.w * wv.w;
            }
            g_hcat[bA * 1024 + c * 8 + jA] = a;
            if (c < 32) qs[bA * 8 + jA] = a;
        }
        if (c < 32) {
            __syncthreads();
#pragma unroll
            for (int rep = 0; rep < 8; rep++) {
                int bs = rep * 256 + tid;
                int b = bs >> 6;
                float a = 0.f;
#pragma unroll
                for (int j = 0; j < 8; j++) {
                    float v = qs[b * 8 + j] + annp[j * 2048 + bs];
                    a += W2s[c * 8 + j] * fmaxf(v, 0.f);
                }
                g_upart[c * 2048 + bs] = a;
            }
        }
        grid_barrier();

        // ---- Phase B ----
        {
            int s = tid & 63, q = tid >> 6;
            float u = 0.f;
#pragma unroll
            for (int cc = q * 8; cc < q * 8 + 8; cc++)
                u += g_upart[cc * 2048 + myb * 64 + s];
            usq[q][s] = u;
        }
        __syncthreads();
        if (tid < 32) {
            float v0 = usq[0][tid] + usq[1][tid] + usq[2][tid] + usq[3][tid];
            int t2 = tid + 32;
            float v1 = usq[0][t2] + usq[1][t2] + usq[2][t2] + usq[3][t2];
            float m = fmaxf(v0, v1);
#pragma unroll
            for (int o = 16; o; o >>= 1) m = fmaxf(m, __shfl_xor_sync(0xffffffffu, m, o));
            float e0 = __expf(v0 - m), e1 = __expf(v1 - m);
            float ssum = e0 + e1;
#pragma unroll
            for (int o = 16; o; o >>= 1) ssum += __shfl_xor_sync(0xffffffffu, ssum, o);
            float inv = 1.f / ssum;
            us[tid] = e0 * inv; us[t2] = e1 * inv;
        }
        __syncthreads();
        if (myds == 0 && tid < 64)
            att_out[(myb * SS + tid) * TT + t] = us[tid];
        if (tid < 192) {
            int g = tid >> 6, dd = tid & 63;
            const float* colp = g_annWi + (size_t)(myb * 64) * 768 + g * 256 + myds * 64 + dd;
            float acc = 0.f;
#pragma unroll 16
            for (int s = 0; s < 64; s++) acc += us[s] * colp[(size_t)s * 768];
            (g == 0 ? gz : g == 1 ? gr : gh)[dd] = acc;
        }
        __syncthreads();
        if (tid < 64) {
            int d = myds * 64 + tid;
            const float* xp = g_xproj + (size_t)(t * 32 + myb) * 768;
            const float* hc = g_hcat + myb * 1024;
            float z  = 1.f / (1.f + __expf(-(gz[tid] + xp[d]       + hc[256 + d])));
            float r  = 1.f / (1.f + __expf(-(gr[tid] + xp[256 + d] + hc[512 + d])));
            float g2 = tanhf(gh[tid] + xp[512 + d] + r * hc[768 + d]);
            float hold = g_hbuf[myb * 256 + d];
            float hn = (1.f - z) * g2 + z * hold;
            g_hbuf[myb * 256 + d] = hn;
            __half hi = __float2half(hn);
            __half lo = __float2half(hn - __half2float(hi));
            size_t rb = (size_t)(myb * 64 + t) * 512;
            g_Ah[rb + d]       = hi;
            g_Ah[rb + 256 + d] = lo;
        }
        grid_barrier();
    }
}

// ---------------------------------------------------------------------------
// K4: HMMA fp16 GEMM  D[2048,32000] = Ah[2048,512] @ Bh[32000,256]^T (B reused)
// tile 128x128, BK=32, 16 k-chunks (B chunk = kt&7), 3-stage cp.async
// ---------------------------------------------------------------------------
#define GSTAGES 3

__global__ void __launch_bounds__(256, 2)
gemm_mma_kernel(const float* __restrict__ bout, float* __restrict__ out) {
    __shared__ __align__(128) __half sA[GSTAGES][128 * 32];
    __shared__ __align__(128) __half sB[GSTAGES][128 * 32];

    const int tid  = threadIdx.x;
    const int lane = tid & 31, wid = tid >> 5;
    const int wr = wid >> 2, wc = wid & 3;
    const int row0 = blockIdx.x * 128, col0 = blockIdx.y * 128;

    const __half* Ag = g_Ah + (size_t)row0 * 512;
    const __half* Bg = g_Bh + (size_t)col0 * 256;

    const uint32_t sAb = smem_u32(sA);
    const uint32_t sBb = smem_u32(sB);

    const int rA0 = tid >> 2,          cA0 = tid & 3;
    const int rA1 = (tid + 256) >> 2;
    const uint32_t dA0 = rA0 * 64 + ((cA0 ^ ((rA0 >> 1) & 3)) * 16);
    const uint32_t dA1 = rA1 * 64 + ((cA0 ^ ((rA1 >> 1) & 3)) * 16);

#define LOAD_STAGE(s, kt) do {                                                       \
        uint32_t ab = sAb + (s) * 8192, bb = sBb + (s) * 8192;                       \
        int bk = ((kt) & 7) * 32;                                                    \
        cp_async16(ab + dA0, Ag + (size_t)rA0 * 512 + (kt) * 32 + cA0 * 8);          \
        cp_async16(ab + dA1, Ag + (size_t)rA1 * 512 + (kt) * 32 + cA0 * 8);          \
        cp_async16(bb + dA0, Bg + (size_t)rA0 * 256 + bk + cA0 * 8);                 \
        cp_async16(bb + dA1, Bg + (size_t)rA1 * 256 + bk + cA0 * 8);                 \
    } while (0)

    LOAD_STAGE(0, 0); CP_COMMIT();
    LOAD_STAGE(1, 1); CP_COMMIT();

    float acc[4][4][4];
#pragma unroll
    for (int i = 0; i < 4; i++)
#pragma unroll
        for (int j = 0; j < 4; j++)
#pragma unroll
            for (int q = 0; q < 4; q++) acc[i][j][q] = 0.f;

    const int aRow = lane & 15;
    const int aSel = lane >> 4;
    const int bRow = (lane & 7) + ((lane >> 4) << 3);
    const int bSel = (lane >> 3) & 1;

#pragma unroll 1
    for (int kt = 0; kt < 16; kt++) {
        CP_WAIT(1);
        __syncthreads();
        if (kt + 2 < 16) LOAD_STAGE((kt + 2) % GSTAGES, kt + 2);
        CP_COMMIT();

        const int st = kt % GSTAGES;
        const uint32_t ab = sAb + st * 8192;
        const uint32_t bb = sBb + st * 8192;

#pragma unroll
        for (int kf = 0; kf < 2; kf++) {
            uint32_t aF[4][4];
#pragma unroll
            for (int mf = 0; mf < 4; mf++) {
                int row = wr * 64 + mf * 16 + aRow;
                int ch  = (kf * 2 + aSel) ^ ((row >> 1) & 3);
                ldsm_x4(ab + row * 64 + ch * 16, aF[mf][0], aF[mf][1], aF[mf][2], aF[mf][3]);
            }
            uint32_t bF[2][4];
#pragma unroll
            for (int nf2 = 0; nf2 < 2; nf2++) {
                int row = wc * 32 + nf2 * 16 + bRow;
                int ch  = (kf * 2 + bSel) ^ ((row >> 1) & 3);
                ldsm_x4(bb + row * 64 + ch * 16, bF[nf2][0], bF[nf2][1], bF[nf2][2], bF[nf2][3]);
            }
#pragma unroll
            for (int mf = 0; mf < 4; mf++)
#pragma unroll
                for (int nf = 0; nf < 4; nf++) {
                    uint32_t b0 = bF[nf >> 1][(nf & 1) * 2 + 0];
                    uint32_t b1 = bF[nf >> 1][(nf & 1) * 2 + 1];
                    mma16816(acc[mf][nf], aF[mf], b0, b1);
                }
        }
        __syncthreads();
    }

    const int rq = lane >> 2, cq = (lane & 3) * 2;
    const int rbase = row0 + wr * 64, cbase = col0 + wc * 32;
#pragma unroll
    for (int mf = 0; mf < 4; mf++) {
#pragma unroll
        for (int nf = 0; nf < 4; nf++) {
            int r  = rbase + mf * 16 + rq;
            int cc = cbase + nf * 8 + cq;
            float bz0 = bout[cc], bz1 = bout[cc + 1];
            float2 v0 = make_float2(acc[mf][nf][0] + bz0, acc[mf][nf][1] + bz1);
            float2 v1 = make_float2(acc[mf][nf][2] + bz0, acc[mf][nf][3] + bz1);
            *(float2*)&out[(size_t)r * VV + cc]       = v0;
            *(float2*)&out[(size_t)(r + 8) * VV + cc] = v1;
        }
    }
#undef LOAD_STAGE
}

// ---------------------------------------------------------------------------
extern "C" void kernel_launch(void* const* d_in, const int* in_sizes, int n_in,
                              void* d_out, int out_size) {
    const int*   inputs = (const int*)  d_in[0];
    const float* ann    = (const float*)d_in[1];
    const float* hinit  = (const float*)d_in[2];
    const float* emb    = (const float*)d_in[3];
    const float* W1     = (const float*)d_in[4];
    const float* b1     = (const float*)d_in[5];
    const float* W2     = (const float*)d_in[6];
    /* b2 (d_in[7]) cancels in softmax */
    const float* Wiz    = (const float*)d_in[8];
    const float* biz    = (const float*)d_in[9];
    const float* Wir    = (const float*)d_in[10];
    const float* bir    = (const float*)d_in[11];
    const float* Wih    = (const float*)d_in[12];
    const float* bih    = (const float*)d_in[13];
    const float* Whz    = (const float*)d_in[14];
    const float* bhz    = (const float*)d_in[15];
    const float* Whr    = (const float*)d_in[16];
    const float* bhr    = (const float*)d_in[17];
    const float* Whh    = (const float*)d_in[18];
    const float* bhh    = (const float*)d_in[19];
    const float* Wout   = (const float*)d_in[20];
    const float* bout   = (const float*)d_in[21];

    float* out = (float*)d_out;
    float* att = out + (size_t)BB * TT * VV;

    static int attr_set = 0;
    if (!attr_set) {
        cudaFuncSetAttribute(recurrence_kernel,
                             cudaFuncAttributeMaxDynamicSharedMemorySize, REC_DSMEM);
        attr_set = 1;
    }

    prep_kernel<<<256, 256>>>(W1, Wiz, Wir, Wih, Whz, bhz, Whr, bhr, Whh, bhh);
    combo_kernel<<<4896, 128>>>(ann, emb, inputs, Wout, b1, biz, bir, bih);
    recurrence_kernel<<<NBLK, 256, REC_DSMEM>>>(hinit, W2, att);
    gemm_mma_kernel<<<dim3(16, 250), 256>>>(bout, out);
}